// round 6
// baseline (speedup 1.0000x reference)
#include <cuda_runtime.h>
#include <cstdint>

#define COLS 16384
#define KSEL 256
#define NT   512
#define EPT  32
#define CAP  2048
#define WCAP 256
#define ROWBYTES (COLS * 4)

// dynamic smem layout
#define OFF_CAND  65536
#define OFF_SLIST (OFF_CAND + CAP * 8)      // 81920
#define OFF_HIST  (OFF_SLIST + WCAP * 8)    // 83968
#define OFF_SCAL  (OFF_HIST + 256 * 4)      // 84992
#define OFF_MBAR  (OFF_SCAL + 32)           // 85024
#define SMEM_TOTAL (OFF_MBAR + 32)          // 85056 -> 2 CTAs/SM fits 227KB

typedef unsigned long long u64;

__device__ __forceinline__ unsigned f2k(float f) {
    unsigned u = __float_as_uint(f);
    return u ^ ((unsigned)((int)u >> 31) | 0x80000000u);
}
__device__ __forceinline__ float k2f(unsigned k) {
    unsigned u = (k & 0x80000000u) ? (k ^ 0x80000000u) : ~k;
    return __uint_as_float(u);
}
__device__ __forceinline__ float k2relu(unsigned k) {
    return (k > 0x80000000u) ? __uint_as_float(k ^ 0x80000000u) : 0.0f;
}
__device__ __forceinline__ unsigned smem_u32(const void* p) {
    unsigned r;
    asm("{ .reg .u64 t; cvta.to.shared.u64 t, %1; cvt.u32.u64 %0, t; }" : "=r"(r) : "l"(p));
    return r;
}
__device__ __forceinline__ void mbar_wait(unsigned mbar, unsigned phase) {
    asm volatile(
        "{\n\t.reg .pred P;\n\t"
        "W%=:\n\t"
        "mbarrier.try_wait.parity.acquire.cta.shared::cta.b64 P, [%0], %1, 0x989680;\n\t"
        "@P bra.uni D%=;\n\t"
        "bra.uni W%=;\n\t"
        "D%=:\n\t}"
        :: "r"(mbar), "r"(phase) : "memory");
}
__device__ __forceinline__ void bulk_load(unsigned sdst, const void* gsrc, unsigned mbar) {
    asm volatile("fence.proxy.async.shared::cta;" ::: "memory");
    asm volatile("mbarrier.arrive.expect_tx.shared.b64 _, [%0], %1;"
                 :: "r"(mbar), "n"(ROWBYTES) : "memory");
    asm volatile("cp.async.bulk.shared::cluster.global.mbarrier::complete_tx::bytes [%0], [%1], %2, [%3];"
                 :: "r"(sdst), "l"(gsrc), "n"(ROWBYTES), "r"(mbar) : "memory");
}

extern __shared__ char smem[];

__global__ void __launch_bounds__(NT, 2)
topk_kernel(const float* __restrict__ x, float* __restrict__ out, int rows, int gsz)
{
    float4*   buf4  = (float4*)smem;
    u64*      cand  = (u64*)(smem + OFF_CAND);
    u64*      slist = (u64*)(smem + OFF_SLIST);
    unsigned* hist  = (unsigned*)(smem + OFF_HIST);
    unsigned* S     = (unsigned*)(smem + OFF_SCAL);  // 0:cnt 1:kmax 2:m 3:j 4:above 5:cntin
    const unsigned mbar = smem_u32(smem + OFF_MBAR);

    const int tid  = threadIdx.x;
    const int lane = tid & 31;
    const int wid  = tid >> 5;

    if (tid == 0)
        asm volatile("mbarrier.init.shared.b64 [%0], 1;" :: "r"(mbar) : "memory");
    __syncthreads();

    const int r0 = blockIdx.x;
    const int nIter = (rows - r0 + gsz - 1) / gsz;
    const unsigned sbuf = smem_u32(smem);

    if (tid == 0) bulk_load(sbuf, x + (size_t)r0 * COLS, mbar);

    unsigned ph = 0;
    for (int j = 0; j < nIter; j++) {
        const size_t row = r0 + (size_t)j * gsz;
        float*  orow  = out + row * COLS;
        float4* orow4 = (float4*)orow;

        // ---- wait for this row's TMA; pull to registers; housekeeping in window ----
        mbar_wait(mbar, ph); ph ^= 1;

        float w[EPT];
        #pragma unroll
        for (int i = 0; i < 8; i++) {
            float4 t = buf4[tid + i * NT];
            w[4*i] = t.x; w[4*i+1] = t.y; w[4*i+2] = t.z; w[4*i+3] = t.w;
        }
        if (tid < 256) hist[tid] = 0;
        if (tid == 0) { S[0] = 0; S[1] = 0; S[2] = 0; }
        float4 z = make_float4(0.f, 0.f, 0.f, 0.f);
        #pragma unroll
        for (int i = 0; i < 8; i++) orow4[tid + i * NT] = z;
        __syncthreads();                                   // (1)

        // ---- prefetch next row into the SAME buffer (regs hold this row) ----
        if (tid == 0 && j + 1 < nIter)
            bulk_load(sbuf, x + (row + (size_t)gsz) * COLS, mbar);

        // ---- row max ----
        float fm = w[0];
        #pragma unroll
        for (int e = 1; e < EPT; e++) fm = fmaxf(fm, w[e]);
        #pragma unroll
        for (int off = 16; off; off >>= 1)
            fm = fmaxf(fm, __shfl_down_sync(0xFFFFFFFFu, fm, off));
        if (lane == 0) atomicMax(&S[1], f2k(fm));

        // ---- scan-based candidate push (one atomic/warp); fallback from regs ----
        unsigned kT = f2k(1.9f);
        float Tf = 1.9f;
        unsigned C = 0;
        unsigned aLo = 0u, bHi = 0xFFFFFFFFu;
        for (int att = 0; att < 34; att++) {
            unsigned c = 0;
            #pragma unroll
            for (int e = 0; e < EPT; e++) c += (w[e] >= Tf);
            unsigned sc = c;
            #pragma unroll
            for (int d = 1; d < 32; d <<= 1) {
                unsigned n = __shfl_up_sync(0xFFFFFFFFu, sc, d);
                if (lane >= d) sc += n;
            }
            unsigned wtot = __shfl_sync(0xFFFFFFFFu, sc, 31);
            unsigned base = 0;
            if (lane == 0 && wtot) base = atomicAdd(&S[0], wtot);
            base = __shfl_sync(0xFFFFFFFFu, base, 0);
            unsigned p = base + (sc - c);
            if (c) {
                #pragma unroll
                for (int e = 0; e < EPT; e++) {
                    if (w[e] >= Tf) {
                        unsigned idx = 4u * (unsigned)(tid + (e >> 2) * NT) + (e & 3);
                        if (p < CAP) cand[p] = ((u64)f2k(w[e]) << 32) | (unsigned)~idx;
                        p++;
                    }
                }
            }
            __syncthreads();                               // (2)
            C = S[0];
            if (C >= KSEL && C <= CAP) break;
            if (C > CAP) aLo = kT; else bHi = kT;
            unsigned nkT = aLo + ((bHi - aLo) >> 1);
            if (nkT == kT) break;
            kT = nkT; Tf = k2f(kT);
            __syncthreads();
            if (tid == 0) S[0] = 0;
            __syncthreads();
        }
        if (C > CAP) C = CAP;
        unsigned kmax = S[1];
        unsigned need = (KSEL < C) ? KSEL : C;

        unsigned winLo = kT;
        unsigned span  = kmax + 1u - kT;
        int sh = (span > 1u) ? (32 - __clz(span - 1u) - 8) : 0;
        if (sh < 0) sh = 0;
        unsigned W = 1u << sh;

        if (C > 0) {
            // ---- 256-bin histogram narrowing; warp0-only suffix scan ----
            for (int r = 0; r < 4; r++) {
                if (r > 0) {
                    if (tid < 256) hist[tid] = 0;
                    __syncthreads();
                }
                for (unsigned p = tid; p < C; p += NT) {
                    unsigned k = (unsigned)(cand[p] >> 32);
                    unsigned d = k - winLo;
                    if ((d >> sh) < 256u) atomicAdd(&hist[d >> sh], 1u);
                }
                __syncthreads();                           // (3)
                if (wid == 0) {
                    uint4 a = *(uint4*)&hist[8 * lane];
                    uint4 b = *(uint4*)&hist[8 * lane + 4];
                    unsigned s7 = b.w;
                    unsigned s6 = b.z + s7, s5 = b.y + s6, s4 = b.x + s5;
                    unsigned s3 = a.w + s4, s2 = a.z + s3, s1 = a.y + s2, s0 = a.x + s1;
                    unsigned suf = s0;
                    #pragma unroll
                    for (int d = 1; d < 32; d <<= 1) {
                        unsigned n = __shfl_down_sync(0xFFFFFFFFu, suf, d);
                        if (lane + d < 32) suf += n;
                    }
                    unsigned add = suf - s0;   // = suffix starting at bin 8*lane+8
                    unsigned sv[8] = { s0, s1, s2, s3, s4, s5, s6, s7 };
                    #pragma unroll
                    for (int i = 0; i < 8; i++) {
                        unsigned Sv = sv[i] + add;
                        unsigned Sn = (i < 7) ? (sv[i + 1] + add) : add;
                        if (Sv >= need && Sn < need) {
                            S[3] = 8u * lane + i; S[4] = Sn; S[5] = Sv - Sn;
                        }
                    }
                }
                __syncthreads();                           // (4)
                unsigned jbin = S[3], nab = S[4], cnt_in = S[5];
                winLo += jbin << sh;
                need  -= nab;
                W = 1u << sh;
                if (cnt_in <= 32u || sh == 0) break;
                sh = (sh >= 8) ? sh - 8 : 0;
            }

            // ---- final pass: write sure winners; gather boundary window ----
            u64 fHi = (u64)winLo + (u64)W;
            for (unsigned p = tid; p < C; p += NT) {
                u64 ck = cand[p];
                unsigned k = (unsigned)(ck >> 32);
                if ((u64)k >= fHi) {
                    orow[~(unsigned)ck] = k2relu(k);
                } else if (k >= winLo) {
                    unsigned q = atomicAdd(&S[2], 1u);
                    if (q < WCAP) slist[q] = ck;
                }
            }
            __syncthreads();                               // (5)
            unsigned m = S[2]; if (m > WCAP) m = WCAP;

            // exact stable rank on tiny window (higher key, lower index on tie)
            for (unsigned p = tid; p < m; p += NT) {
                u64 mine = slist[p];
                unsigned rk = 0;
                for (unsigned q = 0; q < m; q++) rk += (slist[q] > mine);
                if (rk < need)
                    orow[~(unsigned)mine] = k2relu((unsigned)(mine >> 32));
            }
        }
        __syncthreads();                                   // (6) protect S/slist reuse
    }
}

extern "C" void kernel_launch(void* const* d_in, const int* in_sizes, int n_in,
                              void* d_out, int out_size) {
    const float* x = (const float*)d_in[0];
    float* out = (float*)d_out;
    int rows = in_sizes[0] / COLS;

    int dev = 0, sms = 0;
    cudaGetDevice(&dev);
    cudaDeviceGetAttribute(&sms, cudaDevAttrMultiProcessorCount, dev);
    if (sms <= 0) sms = 148;
    int gsz = 2 * sms;
    if (gsz > rows) gsz = rows;

    cudaFuncSetAttribute(topk_kernel, cudaFuncAttributeMaxDynamicSharedMemorySize, SMEM_TOTAL);
    topk_kernel<<<gsz, NT, SMEM_TOTAL>>>(x, out, rows, gsz);
}

// round 7
// speedup vs baseline: 1.0987x; 1.0987x over previous
#include <cuda_runtime.h>
#include <cstdint>

#define COLS 16384
#define KSEL 256
#define NT   512
#define EPT  32
#define WCAP 512

typedef unsigned long long u64;

__global__ void __launch_bounds__(NT, 2)
topk_kernel(const float* __restrict__ x, float* __restrict__ out)
{
    __shared__ unsigned hist[256];
    __shared__ u64 slist[WCAP];
    __shared__ unsigned S[8];   // 2:m 3:jbin 4:nab 5:cnt_in 6:total

    const int tid = threadIdx.x, lane = tid & 31, wid = tid >> 5;
    const size_t row = blockIdx.x;
    const float4* __restrict__ xr4 = (const float4*)(x + row * COLS);
    float* __restrict__ orow = out + row * COLS;
    float4* __restrict__ orow4 = (float4*)orow;

    if (tid < 256) hist[tid] = 0;
    if (tid == 0) S[2] = 0;

    // front-batched LDG.128 (MLP=8/warp)
    float w[EPT];
    #pragma unroll
    for (int i = 0; i < 8; i++) {
        float4 t = xr4[tid + i * NT];
        w[4*i]=t.x; w[4*i+1]=t.y; w[4*i+2]=t.z; w[4*i+3]=t.w;
    }
    __syncthreads();                                       // (1)

    // selection window in positive-float-bits space
    unsigned winB = 0x3FF33333u;             // bits(1.9f): ~470 expected candidates
    unsigned span = 0x7F800001u - winB;      // through +inf (top bin clamped)
    int      sh   = 17;                      // fine bins where N(0,1) boundary lives
    unsigned need = KSEL;
    unsigned bLo = 0xFFFFFFFFu, bThr = 0xFFFFFFFFu;  // safe defaults: select nothing
    bool fellback = false;

    for (int r = 0; r < 12; r++) {
        // histogram straight from registers (negatives/zero auto-excluded by wrap)
        #pragma unroll
        for (int e = 0; e < EPT; e++) {
            unsigned d = __float_as_uint(w[e]) - winB;
            if (d < span) {
                unsigned b = d >> sh;
                if (b > 255u) b = 255u;
                atomicAdd(&hist[b], 1u);
            }
        }
        __syncthreads();                                   // (2)

        // warp0: suffix sums over 256 bins + boundary find
        if (wid == 0) {
            uint4 a = *(uint4*)&hist[8*lane];
            uint4 b = *(uint4*)&hist[8*lane+4];
            unsigned s7=b.w, s6=b.z+s7, s5=b.y+s6, s4=b.x+s5;
            unsigned s3=a.w+s4, s2=a.z+s3, s1=a.y+s2, s0=a.x+s1;
            unsigned suf = s0;
            #pragma unroll
            for (int d = 1; d < 32; d <<= 1) {
                unsigned n = __shfl_down_sync(0xFFFFFFFFu, suf, d);
                if (lane + d < 32) suf += n;
            }
            if (lane == 0) S[6] = suf;                     // total candidates
            unsigned add = suf - s0;                       // suffix beyond this lane's 8 bins
            unsigned sv[8] = {s0,s1,s2,s3,s4,s5,s6,s7};
            #pragma unroll
            for (int i = 0; i < 8; i++) {
                unsigned Sv = sv[i] + add;
                unsigned Sn = (i < 7) ? (sv[i+1] + add) : add;
                if (Sv >= need && Sn < need) { S[3]=8u*lane+i; S[4]=Sn; S[5]=Sv-Sn; }
            }
        }
        __syncthreads();                                   // (3)

        unsigned C = S[6];
        if (C < need && !fellback) {
            // too few above 1.9: re-histogram over ALL positives.
            // (negative/zero top-K entries are ReLU'd to 0 == background, so
            //  only positives ever need exact selection)
            fellback = true;
            winB = 1u; span = 0x7F800000u; sh = 23;
            if (tid < 256) hist[tid] = 0;
            __syncthreads();
            continue;
        }
        if (C <= need) { bLo = winB; bThr = winB; break; } // every candidate wins

        unsigned jbin = S[3], nab = S[4], cnt_in = S[5];
        bool clamped = ((span - 1u) >> sh) > 255u;
        unsigned newLo = winB + ((unsigned)jbin << sh);
        unsigned newSpan = (clamped && jbin == 255u) ? (span - (255u << sh))
                                                     : (1u << sh);
        need -= nab;
        if (cnt_in <= 32u || sh == 0) { bLo = newLo; bThr = newLo + newSpan; break; }
        winB = newLo; span = newSpan;
        int nsh = 32 - __clz(newSpan - 1u) - 8;            // proper 256-way split
        sh = (nsh < 0) ? 0 : nsh;
        if (tid < 256) hist[tid] = 0;
        __syncthreads();
    }

    // ---- fused output write: zeros + sure winners + boundary gather, one pass ----
    const unsigned thrSpan = 0x80000000u - bThr;  // [bThr, 0x80000000) = positive & >= bThr
    const unsigned winSpan = bThr - bLo;          // boundary window (0 in all-win case)
    const unsigned base4 = 4u * (unsigned)tid;
    #pragma unroll
    for (int i = 0; i < 8; i++) {
        float vv[4];
        #pragma unroll
        for (int c = 0; c < 4; c++) {
            const int e = 4*i + c;
            float f = w[e];
            unsigned bits = __float_as_uint(f);
            vv[c] = ((bits - bThr) < thrSpan) ? f : 0.0f;
            unsigned dw = bits - bLo;
            if (dw < winSpan) {                   // rare: boundary-bin element
                unsigned p = atomicAdd(&S[2], 1u);
                unsigned idx = base4 + (unsigned)(i * (NT * 4)) + (unsigned)c;
                if (p < WCAP) slist[p] = ((u64)bits << 32) | (unsigned)~idx;
            }
        }
        orow4[tid + i * NT] = make_float4(vv[0], vv[1], vv[2], vv[3]);
    }
    __syncthreads();                                       // (4)

    // ---- exact stable rank on tiny boundary window (key desc, index asc) ----
    unsigned m = S[2]; if (m > WCAP) m = WCAP;
    for (unsigned p = tid; p < m; p += NT) {
        u64 mine = slist[p];
        unsigned rk = 0;
        for (unsigned q = 0; q < m; q++) rk += (slist[q] > mine);
        if (rk < need)
            orow[~(unsigned)mine] = __uint_as_float((unsigned)(mine >> 32));
    }
}

extern "C" void kernel_launch(void* const* d_in, const int* in_sizes, int n_in,
                              void* d_out, int out_size) {
    const float* x = (const float*)d_in[0];
    float* out = (float*)d_out;
    int rows = in_sizes[0] / COLS;
    topk_kernel<<<rows, NT>>>(x, out);
}